// round 1
// baseline (speedup 1.0000x reference)
#include <cuda_runtime.h>
#include <cstdint>

// Problem dims
#define BB   64
#define SS   512
#define NHH  4
#define DD   256
#define HH   256
#define MROWS (BB*SS*NHH)   // 131072

// ---------------- device scratch (static, allocation-free) ----------------
__device__ float g_kxW[(size_t)MROWS * 256];   // x @ (Wk@Wcomb) + bias   (134MB)
__device__ float g_xW1[(size_t)MROWS * 256];   // x @ W1_top + b1 + bproj@W1bot (134MB)
__device__ float g_kscore[MROWS];
__device__ float g_Wcomb[256 * 256];           // Wproj @ W1_bot
__device__ float g_Wbig[256 * 512];            // [Wk@Wcomb | W1_top]  (K=256 rows, N=512)
__device__ float g_bias[512];                  // [bk@Wcomb | b1 + bproj@W1bot]
__device__ float g_vq[256];                    // Wq @ w2
__device__ float g_wk1[256];                   // Wk @ w1
__device__ float g_w2v[256];                   // W2 @ vq
__device__ float g_scalars[4];                 // [cq=bq·w2, ck1=bk·w1, c2=b2·vq+cq]
__device__ float g_h1[BB * NHH * 256];         // relu pre-activation at final step
__device__ float g_hidden[BB * NHH * 256];     // final hidden

// ---------------- small setup kernels ----------------
__global__ void k_setup1(const float* __restrict__ Wk, const float* __restrict__ bk,
                         const float* __restrict__ Wq, const float* __restrict__ bq,
                         const float* __restrict__ w_mlp) {
    __shared__ float sw1[256], sw2[256];
    int tid = threadIdx.x;
    sw1[tid] = w_mlp[tid];
    sw2[tid] = w_mlp[256 + tid];
    __syncthreads();
    float vq = 0.f, wk1 = 0.f;
    for (int h = 0; h < 256; h++) {
        vq  += Wq[tid * 256 + h] * sw2[h];
        wk1 += Wk[tid * 256 + h] * sw1[h];
    }
    g_vq[tid] = vq;
    g_wk1[tid] = wk1;
    if (tid == 0) {
        float cq = 0.f, ck1 = 0.f;
        for (int h = 0; h < 256; h++) { cq += bq[h] * sw2[h]; ck1 += bk[h] * sw1[h]; }
        g_scalars[0] = cq;
        g_scalars[1] = ck1;
    }
}

// Wcomb[h][n] = sum_h' Wproj[h][h'] * W1[256+h'][n]
__global__ void k_wcomb(const float* __restrict__ Wproj, const float* __restrict__ W1) {
    __shared__ float sp[256];
    int h = blockIdx.x, tid = threadIdx.x;
    sp[tid] = Wproj[h * 256 + tid];
    __syncthreads();
    float acc = 0.f;
    for (int hp = 0; hp < 256; hp++)
        acc += sp[hp] * W1[(256 + hp) * 256 + tid];
    g_Wcomb[h * 256 + tid] = acc;
}

// assemble g_Wbig, g_bias, g_w2v, c2
__global__ void k_wkc(const float* __restrict__ Wk, const float* __restrict__ W1,
                      const float* __restrict__ bk, const float* __restrict__ b1,
                      const float* __restrict__ bproj, const float* __restrict__ W2,
                      const float* __restrict__ b2) {
    int tid = threadIdx.x;
    if (blockIdx.x < 256) {
        int d = blockIdx.x;
        __shared__ float s[256];
        s[tid] = Wk[d * 256 + tid];
        __syncthreads();
        float acc = 0.f;
        for (int h = 0; h < 256; h++) acc += s[h] * g_Wcomb[h * 256 + tid];
        g_Wbig[d * 512 + tid]       = acc;               // Wk @ Wcomb
        g_Wbig[d * 512 + 256 + tid] = W1[d * 256 + tid]; // W1_top copy
    } else {
        float a = 0.f, bb = 0.f, w = 0.f;
        for (int h = 0; h < 256; h++) a  += bk[h]    * g_Wcomb[h * 256 + tid];
        for (int h = 0; h < 256; h++) bb += bproj[h] * W1[(256 + h) * 256 + tid];
        for (int h = 0; h < 256; h++) w  += W2[tid * 256 + h] * g_vq[h];
        g_bias[tid]       = a;
        g_bias[256 + tid] = b1[tid] + bb;
        g_w2v[tid] = w;
        if (tid == 0) {
            float c2 = 0.f;
            for (int h = 0; h < 256; h++) c2 += b2[h] * g_vq[h];
            g_scalars[2] = c2 + g_scalars[0];
        }
    }
}

// ---------------- big GEMM: C(131072x512) = X(131072x256) @ g_Wbig(256x512) + bias ----
// BM=128 BN=128 BK=8 TM=8 TN=8, 256 threads
__global__ void __launch_bounds__(256) k_gemm(const float* __restrict__ A) {
    __shared__ float As[8][128];
    __shared__ float Bs[8][128];
    const int cCol = blockIdx.x;   // 0..3
    const int cRow = blockIdx.y;   // 0..1023
    const int tid = threadIdx.x;
    const int tx = tid & 15, ty = tid >> 4;
    const int aRow = tid >> 1, aCol = (tid & 1) << 2;
    const int bRow = tid >> 5, bCol = (tid & 31) << 2;
    const float* Ab = A + (size_t)cRow * 128 * 256;
    const float* Bb = g_Wbig + cCol * 128;
    float acc[8][8];
#pragma unroll
    for (int i = 0; i < 8; i++)
#pragma unroll
        for (int j = 0; j < 8; j++) acc[i][j] = 0.f;
    float regM[8], regN[8];
    for (int k0 = 0; k0 < 256; k0 += 8) {
        float4 a4 = *reinterpret_cast<const float4*>(Ab + (size_t)aRow * 256 + k0 + aCol);
        As[aCol + 0][aRow] = a4.x;
        As[aCol + 1][aRow] = a4.y;
        As[aCol + 2][aRow] = a4.z;
        As[aCol + 3][aRow] = a4.w;
        *reinterpret_cast<float4*>(&Bs[bRow][bCol]) =
            *reinterpret_cast<const float4*>(Bb + (size_t)(k0 + bRow) * 512 + bCol);
        __syncthreads();
#pragma unroll
        for (int k = 0; k < 8; k++) {
#pragma unroll
            for (int i = 0; i < 8; i++) regM[i] = As[k][ty * 8 + i];
#pragma unroll
            for (int j = 0; j < 8; j++) regN[j] = Bs[k][tx * 8 + j];
#pragma unroll
            for (int i = 0; i < 8; i++)
#pragma unroll
                for (int j = 0; j < 8; j++) acc[i][j] += regM[i] * regN[j];
        }
        __syncthreads();
    }
    float* Cout = (cCol < 2) ? g_kxW : g_xW1;
    const int colbase = (cCol & 1) * 128 + tx * 8;
    const int biasbase = cCol * 128 + tx * 8;
#pragma unroll
    for (int i = 0; i < 8; i++) {
        size_t row = (size_t)cRow * 128 + ty * 8 + i;
#pragma unroll
        for (int j4 = 0; j4 < 8; j4 += 4) {
            float4 v;
            v.x = acc[i][j4 + 0] + g_bias[biasbase + j4 + 0];
            v.y = acc[i][j4 + 1] + g_bias[biasbase + j4 + 1];
            v.z = acc[i][j4 + 2] + g_bias[biasbase + j4 + 2];
            v.w = acc[i][j4 + 3] + g_bias[biasbase + j4 + 3];
            *reinterpret_cast<float4*>(&Cout[row * 256 + colbase + j4]) = v;
        }
    }
}

// ---------------- kscore GEMV: one warp per row ----------------
__global__ void k_kscore(const float* __restrict__ X) {
    int warp = threadIdx.x >> 5, lane = threadIdx.x & 31;
    size_t row = (size_t)blockIdx.x * 8 + warp;
    const float4* xp = reinterpret_cast<const float4*>(X + row * 256);
    const float4* wp = reinterpret_cast<const float4*>(g_wk1);
    float4 a = xp[lane], w = wp[lane];
    float d = a.x * w.x + a.y * w.y + a.z * w.z + a.w * w.w;
    float4 a2 = xp[lane + 32], w2 = wp[lane + 32];
    d += a2.x * w2.x + a2.y * w2.y + a2.z * w2.z + a2.w * w2.w;
#pragma unroll
    for (int off = 16; off; off >>= 1) d += __shfl_down_sync(0xFFFFFFFFu, d, off);
    if (lane == 0) g_kscore[row] = d + g_scalars[1];
}

// ---------------- recurrent scan: one CTA per batch element ----------------
__device__ __forceinline__ void cp16(float* s, const float* g) {
    uint32_t sa = (uint32_t)__cvta_generic_to_shared(s);
    asm volatile("cp.async.ca.shared.global [%0], [%1], 16;" :: "r"(sa), "l"(g));
}

__global__ void __launch_bounds__(256) k_recurrent() {
    const int b = blockIdx.x;
    const int tid = threadIdx.x;
    const int lane = tid & 31, wid = tid >> 5;
    __shared__ __align__(16) float sk[2][1024];
    __shared__ __align__(16) float sx[2][1024];
    __shared__ __align__(16) float sks[2][4];
    __shared__ float qs[4];
    __shared__ float ps[16];
    __shared__ float wp[8][4];

    const float w2vh = g_w2v[tid];
    const float c2 = g_scalars[2];
    if (tid < 4) qs[tid] = g_scalars[0];  // hidden=0 -> qscore = cq

    // prime stages t=0 (buf0) and t=1 (buf1)
    {
        size_t base0 = ((size_t)b * 512 + 0) * 4 * 256;
        cp16(&sk[0][tid * 4], g_kxW + base0 + (size_t)tid * 4);
        cp16(&sx[0][tid * 4], g_xW1 + base0 + (size_t)tid * 4);
        if (tid == 0) cp16(sks[0], g_kscore + ((size_t)b * 512 + 0) * 4);
        asm volatile("cp.async.commit_group;" ::: "memory");
        size_t base1 = ((size_t)b * 512 + 1) * 4 * 256;
        cp16(&sk[1][tid * 4], g_kxW + base1 + (size_t)tid * 4);
        cp16(&sx[1][tid * 4], g_xW1 + base1 + (size_t)tid * 4);
        if (tid == 0) cp16(sks[1], g_kscore + ((size_t)b * 512 + 1) * 4);
        asm volatile("cp.async.commit_group;" ::: "memory");
    }
    __syncthreads();

    for (int t = 0; t < 512; t++) {
        const int buf = t & 1;
        asm volatile("cp.async.wait_group 1;" ::: "memory");
        __syncthreads();  // A: stage ready + qs current

        if (tid < 16) {
            int i = tid >> 2;
            float s = tanhf(qs[i] + sks[buf][tid & 3]);
            float m = fmaxf(s, __shfl_xor_sync(0xFFFFu, s, 1));
            m = fmaxf(m, __shfl_xor_sync(0xFFFFu, m, 2));
            float e = __expf(s - m);
            float sum = e + __shfl_xor_sync(0xFFFFu, e, 1);
            sum += __shfl_xor_sync(0xFFFFu, sum, 2);
            ps[tid] = e / sum;
        }
        __syncthreads();  // B: ps visible

        const float k0 = sk[buf][tid], k1 = sk[buf][256 + tid],
                    k2 = sk[buf][512 + tid], k3 = sk[buf][768 + tid];
        float a0, a1, a2, a3;
        {
            float v = sx[buf][tid] + ps[0] * k0 + ps[1] * k1 + ps[2] * k2 + ps[3] * k3;
            float h = fmaxf(v, 0.f);
            if (t == 511) g_h1[(b * 4 + 0) * 256 + tid] = h;
            a0 = h * w2vh;
        }
        {
            float v = sx[buf][256 + tid] + ps[4] * k0 + ps[5] * k1 + ps[6] * k2 + ps[7] * k3;
            float h = fmaxf(v, 0.f);
            if (t == 511) g_h1[(b * 4 + 1) * 256 + tid] = h;
            a1 = h * w2vh;
        }
        {
            float v = sx[buf][512 + tid] + ps[8] * k0 + ps[9] * k1 + ps[10] * k2 + ps[11] * k3;
            float h = fmaxf(v, 0.f);
            if (t == 511) g_h1[(b * 4 + 2) * 256 + tid] = h;
            a2 = h * w2vh;
        }
        {
            float v = sx[buf][768 + tid] + ps[12] * k0 + ps[13] * k1 + ps[14] * k2 + ps[15] * k3;
            float h = fmaxf(v, 0.f);
            if (t == 511) g_h1[(b * 4 + 3) * 256 + tid] = h;
            a3 = h * w2vh;
        }
#pragma unroll
        for (int off = 16; off; off >>= 1) {
            a0 += __shfl_down_sync(0xFFFFFFFFu, a0, off);
            a1 += __shfl_down_sync(0xFFFFFFFFu, a1, off);
            a2 += __shfl_down_sync(0xFFFFFFFFu, a2, off);
            a3 += __shfl_down_sync(0xFFFFFFFFu, a3, off);
        }
        if (lane == 0) { wp[wid][0] = a0; wp[wid][1] = a1; wp[wid][2] = a2; wp[wid][3] = a3; }
        __syncthreads();  // C: wp visible, buf free for reuse

        if (t + 2 < 512) {
            size_t base = ((size_t)b * 512 + t + 2) * 4 * 256;
            cp16(&sk[buf][tid * 4], g_kxW + base + (size_t)tid * 4);
            cp16(&sx[buf][tid * 4], g_xW1 + base + (size_t)tid * 4);
            if (tid == 0) cp16(sks[buf], g_kscore + ((size_t)b * 512 + t + 2) * 4);
        }
        asm volatile("cp.async.commit_group;" ::: "memory");

        if (tid < 4) {
            float s = c2;
#pragma unroll
            for (int w = 0; w < 8; w++) s += wp[w][tid];
            qs[tid] = s;  // published by sync A next iter
        }
    }
}

// ---------------- epilogue ----------------
__global__ void k_hfinal(const float* __restrict__ W2, const float* __restrict__ b2,
                         float* __restrict__ out) {
    int r = blockIdx.x, tid = threadIdx.x;
    __shared__ float sh[256];
    sh[tid] = g_h1[r * 256 + tid];
    __syncthreads();
    float acc = b2[tid];
    for (int h = 0; h < 256; h++) acc += sh[h] * W2[h * 256 + tid];
    g_hidden[r * 256 + tid] = acc;
    out[192 + r * 256 + tid] = acc;  // h_final after the 192 logits outputs
}

__global__ void k_logits(const float* __restrict__ Wo, const float* __restrict__ bo,
                         float* __restrict__ out) {
    int bidx = blockIdx.x, tid = threadIdx.x, lane = tid & 31, wid = tid >> 5;
    __shared__ float red[4][3];
    float p0 = 0.f, p1 = 0.f, p2 = 0.f;
    for (int k = tid; k < 1024; k += 128) {
        float h = g_hidden[bidx * 1024 + k];
        p0 += h * Wo[k * 3 + 0];
        p1 += h * Wo[k * 3 + 1];
        p2 += h * Wo[k * 3 + 2];
    }
#pragma unroll
    for (int off = 16; off; off >>= 1) {
        p0 += __shfl_down_sync(0xFFFFFFFFu, p0, off);
        p1 += __shfl_down_sync(0xFFFFFFFFu, p1, off);
        p2 += __shfl_down_sync(0xFFFFFFFFu, p2, off);
    }
    if (lane == 0) { red[wid][0] = p0; red[wid][1] = p1; red[wid][2] = p2; }
    __syncthreads();
    if (tid == 0) {
        float l0 = bo[0], l1 = bo[1], l2 = bo[2];
        for (int w = 0; w < 4; w++) { l0 += red[w][0]; l1 += red[w][1]; l2 += red[w][2]; }
        float m = fmaxf(l0, fmaxf(l1, l2));
        float lse = m + logf(expf(l0 - m) + expf(l1 - m) + expf(l2 - m));
        out[bidx * 3 + 0] = l0 - lse;
        out[bidx * 3 + 1] = l1 - lse;
        out[bidx * 3 + 2] = l2 - lse;
    }
}

// ---------------- launch ----------------
extern "C" void kernel_launch(void* const* d_in, const int* in_sizes, int n_in,
                              void* d_out, int out_size) {
    const float* x     = (const float*)d_in[0];
    const float* Wk    = (const float*)d_in[1];
    const float* bk    = (const float*)d_in[2];
    const float* Wq    = (const float*)d_in[3];
    const float* bq    = (const float*)d_in[4];
    const float* w_mlp = (const float*)d_in[5];
    const float* Wproj = (const float*)d_in[6];
    const float* bproj = (const float*)d_in[7];
    const float* W1    = (const float*)d_in[8];
    const float* b1    = (const float*)d_in[9];
    const float* W2    = (const float*)d_in[10];
    const float* b2    = (const float*)d_in[11];
    const float* Wo    = (const float*)d_in[12];
    const float* bo    = (const float*)d_in[13];
    float* out = (float*)d_out;

    k_setup1<<<1, 256>>>(Wk, bk, Wq, bq, w_mlp);
    k_wcomb<<<256, 256>>>(Wproj, W1);
    k_wkc<<<257, 256>>>(Wk, W1, bk, b1, bproj, W2, b2);
    k_gemm<<<dim3(4, 1024), 256>>>(x);
    k_kscore<<<16384, 256>>>(x);
    k_recurrent<<<64, 256>>>();
    k_hfinal<<<256, 256>>>(W2, b2, out);
    k_logits<<<64, 128>>>(Wo, bo, out);
}